// round 5
// baseline (speedup 1.0000x reference)
#include <cuda_runtime.h>

// HashEncoding (instant-NGP multires hash grid), sm_103a.
// R4 profile: L1tex 95% -> cost == gather lines. R5: for dense levels 0-8,
// pack all 8 cell corners into one 64B (one-L1-line) record; 4 lanes
// cooperatively load it (one LDG.128 each = quarter), reduce via shfl.
// Dense cost: 4 -> 1 line per (point,level). Lines: 92M -> ~65M.

#define TABLE_SIZE (1u << 19)
#define HASH_MASK  (TABLE_SIZE - 1u)
#define P1 2654435761u
#define P2 805459861u
#define N_SMALL 9

// int(16 * 32**(i/15)) with host libm pow: level 9 = 127 (confirmed in R1/R2).
__constant__ int d_res[16] = {16, 20, 25, 32, 40, 50, 64, 80,
                              101, 127, 161, 203, 256, 322, 406, 512};
// cumulative r^3 record offsets for levels 0..8
__constant__ int d_start[N_SMALL] = {0, 4096, 12096, 27721, 60489,
                                     124489, 249489, 511633, 1023633};
#define DENSE_TOTAL 2053934

// per-corner features (phase-1 temp), 16.4 MB
__device__ float2 g_corner[DENSE_TOTAL];
// 8-corner records: 4 float4 quarters per cell, 131 MB
__device__ float4 g_dense[(size_t)DENSE_TOTAL * 4];

// q = trunc(((c/res + 1) * 0.5) * 2^18); division as div.full.f32 to match
// the XLA-GPU reference's fast-path lowering (bit-exact requirement, R3).
__device__ __forceinline__ unsigned qval(int c, float resf) {
    float d;
    asm("div.full.f32 %0, %1, %2;" : "=f"(d) : "f"((float)c), "f"(resf));
    float v = __fmul_rn(__fadd_rn(d, 1.0f), 131072.0f);
    return (unsigned)v;
}

// Phase 1: one hashed gather per unique dense corner -> g_corner (coalesced writes).
__global__ __launch_bounds__(256)
void pre_corners(const float2* __restrict__ tables) {
    int level = blockIdx.y;
    int r = d_res[level];
    int n = r * r * r;
    int i = blockIdx.x * blockDim.x + threadIdx.x;
    if (i >= n) return;
    int c = i % r;
    int t = i / r;
    int b = t % r;
    int a = t / r;
    float resf = (float)r;
    unsigned h = qval(a, resf) + qval(b, resf) * P1 + qval(c, resf) * P2;
    const float2* tab = tables + (size_t)level * TABLE_SIZE;
    g_corner[d_start[level] + i] = __ldg(&tab[h & HASH_MASK]);
}

// Phase 2: assemble 64B records from the corner temp (coalesced reads along c).
__global__ __launch_bounds__(256)
void pre_records() {
    int level = blockIdx.y;
    int r = d_res[level];
    int n = r * r * r;
    int i = blockIdx.x * blockDim.x + threadIdx.x;
    if (i >= n) return;
    int c = i % r;
    int t = i / r;
    int b = t % r;
    int a = t / r;
    int a1 = (a + 1 == r) ? 0 : a + 1;
    int b1 = (b + 1 == r) ? 0 : b + 1;
    int c1 = (c + 1 == r) ? 0 : c + 1;
    const float2* tc = g_corner + d_start[level];
    int r00 = (a * r + b) * r,  r01 = (a * r + b1) * r;
    int r10 = (a1 * r + b) * r, r11 = (a1 * r + b1) * r;
    float2 f000 = tc[r00 + c], f001 = tc[r00 + c1];
    float2 f010 = tc[r01 + c], f011 = tc[r01 + c1];
    float2 f100 = tc[r10 + c], f101 = tc[r10 + c1];
    float2 f110 = tc[r11 + c], f111 = tc[r11 + c1];
    float4* rec = g_dense + (size_t)(d_start[level] + i) * 4;
    rec[0] = make_float4(f000.x, f000.y, f001.x, f001.y);  // q0: (x0,y0)
    rec[1] = make_float4(f010.x, f010.y, f011.x, f011.y);  // q1: (x0,y1)
    rec[2] = make_float4(f100.x, f100.y, f101.x, f101.y);  // q2: (x1,y0)
    rec[3] = make_float4(f110.x, f110.y, f111.x, f111.y);  // q3: (x1,y1)
}

// Main, dense levels 0-8: 4 lanes per (point,level), one LDG.128 each.
__global__ __launch_bounds__(256)
void encode_dense(const float* __restrict__ x,
                  float2* __restrict__ out, int n_pts)
{
    int t = blockIdx.x * blockDim.x + threadIdx.x;
    int q = t & 3;
    int qid = t >> 2;
    if (qid >= n_pts * N_SMALL) return;
    int point = qid / N_SMALL;
    int level = qid - point * N_SMALL;

    float px = fminf(fmaxf(__ldg(x + 3 * point + 0), -1.0f), 1.0f);
    float py = fminf(fmaxf(__ldg(x + 3 * point + 1), -1.0f), 1.0f);
    float pz = fminf(fmaxf(__ldg(x + 3 * point + 2), -1.0f), 1.0f);

    int r = d_res[level];
    float resf = (float)r;
    float cx = __fmul_rn(px, resf);
    float cy = __fmul_rn(py, resf);
    float cz = __fmul_rn(pz, resf);
    float fx = floorf(cx), fy = floorf(cy), fz = floorf(cz);
    float lx = __fsub_rn(cx, fx);
    float ly = __fsub_rn(cy, fy);
    float lz = __fsub_rn(cz, fz);
    int ix = (int)fx, iy = (int)fy, iz = (int)fz;
    int x0 = ix; if (x0 < 0) x0 += r; else if (x0 >= r) x0 -= r;
    int y0 = iy; if (y0 < 0) y0 += r; else if (y0 >= r) y0 -= r;
    int z0 = iz; if (z0 < 0) z0 += r; else if (z0 >= r) z0 -= r;

    size_t rec = (size_t)(d_start[level] + (x0 * r + y0) * r + z0) * 4 + q;
    float4 v = __ldg(&g_dense[rec]);

    float wq = ((q >> 1) ? lx : 1.0f - lx) * ((q & 1) ? ly : 1.0f - ly);
    float wz0 = 1.0f - lz;
    float pax = wq * (wz0 * v.x + lz * v.z);
    float pay = wq * (wz0 * v.y + lz * v.w);
    pax += __shfl_xor_sync(0xFFFFFFFFu, pax, 1);
    pay += __shfl_xor_sync(0xFFFFFFFFu, pay, 1);
    pax += __shfl_xor_sync(0xFFFFFFFFu, pax, 2);
    pay += __shfl_xor_sync(0xFFFFFFFFu, pay, 2);
    if (q == 0) out[(size_t)point * 16 + level] = make_float2(pax, pay);
}

// Main, hash levels 9-15: 8 scattered 8B gathers per (point,level).
__global__ __launch_bounds__(256)
void encode_hash(const float* __restrict__ x,
                 const float2* __restrict__ tables,
                 float2* __restrict__ out, int n_pts)
{
    int t = blockIdx.x * blockDim.x + threadIdx.x;
    if (t >= n_pts * 7) return;
    int point = t / 7;
    int level = 9 + (t - point * 7);

    float px = fminf(fmaxf(__ldg(x + 3 * point + 0), -1.0f), 1.0f);
    float py = fminf(fmaxf(__ldg(x + 3 * point + 1), -1.0f), 1.0f);
    float pz = fminf(fmaxf(__ldg(x + 3 * point + 2), -1.0f), 1.0f);

    int res = d_res[level];
    float resf = (float)res;
    float cx = __fmul_rn(px, resf);
    float cy = __fmul_rn(py, resf);
    float cz = __fmul_rn(pz, resf);
    float fx = floorf(cx), fy = floorf(cy), fz = floorf(cz);
    float lx = __fsub_rn(cx, fx);
    float ly = __fsub_rn(cy, fy);
    float lz = __fsub_rn(cz, fz);
    int ix = (int)fx, iy = (int)fy, iz = (int)fz;

    int x0 = ix;     if (x0 < 0) x0 += res; else if (x0 >= res) x0 -= res;
    int x1 = ix + 1; if (x1 < 0) x1 += res; else if (x1 >= res) x1 -= res;
    int y0 = iy;     if (y0 < 0) y0 += res; else if (y0 >= res) y0 -= res;
    int y1 = iy + 1; if (y1 < 0) y1 += res; else if (y1 >= res) y1 -= res;
    int z0 = iz;     if (z0 < 0) z0 += res; else if (z0 >= res) z0 -= res;
    int z1 = iz + 1; if (z1 < 0) z1 += res; else if (z1 >= res) z1 -= res;

    unsigned hx[2], hy[2], hz[2];
    hx[0] = qval(x0, resf);
    hx[1] = qval(x1, resf);
    hy[0] = qval(y0, resf) * P1;
    hy[1] = qval(y1, resf) * P1;
    hz[0] = qval(z0, resf) * P2;
    hz[1] = qval(z1, resf) * P2;

    const float2* tab = tables + (size_t)level * TABLE_SIZE;
    float2 f[8];
#pragma unroll
    for (int c = 0; c < 8; c++) {
        unsigned idx = (hx[(c >> 2) & 1] + hy[(c >> 1) & 1] + hz[c & 1]) & HASH_MASK;
        f[c] = __ldg(&tab[idx]);
    }
    float wxa[2] = {1.0f - lx, lx};
    float wya[2] = {1.0f - ly, ly};
    float wza[2] = {1.0f - lz, lz};
    float ax = 0.0f, ay = 0.0f;
#pragma unroll
    for (int c = 0; c < 8; c++) {
        float w = wxa[(c >> 2) & 1] * wya[(c >> 1) & 1] * wza[c & 1];
        ax += w * f[c].x;
        ay += w * f[c].y;
    }
    out[(size_t)point * 16 + level] = make_float2(ax, ay);
}

extern "C" void kernel_launch(void* const* d_in, const int* in_sizes, int n_in,
                              void* d_out, int out_size) {
    const float* x = (const float*)d_in[0];
    const float2* tables = (const float2*)d_in[1];
    float2* out = (float2*)d_out;
    int n_pts = in_sizes[0] / 3;

    dim3 pre_grid((1030301 + 255) / 256, N_SMALL);   // max r^3 = 101^3
    pre_corners<<<pre_grid, 256>>>(tables);
    pre_records<<<pre_grid, 256>>>();

    long long nd = (long long)n_pts * N_SMALL * 4;
    encode_dense<<<(int)((nd + 255) / 256), 256>>>(x, out, n_pts);

    long long nh = (long long)n_pts * 7;
    encode_hash<<<(int)((nh + 255) / 256), 256>>>(x, tables, out, n_pts);
}

// round 6
// speedup vs baseline: 1.0448x; 1.0448x over previous
#include <cuda_runtime.h>

// HashEncoding (instant-NGP multires hash grid), sm_103a.
// Governing law (R3-R5): dur ~= L1tex gather-lines / 148 SMs / clock
// (~0.94 cyc/line at the wavefront floor), provided the gather set is
// L2-resident (R5 showed DRAM-resident records crater to latency-bound).
//
// R6: per (level<9, x,y,z) store a 32B "quad" record = features of
// {(y,z),(y,z+1),(y+1,z),(y+1,z+1)} at fixed x. 4x duplication -> 66MB,
// L2-resident. A point-level loads quads at x0 and x1 via 4 lanes x
// LDG.128 (records 32B-aligned -> never straddle a 128B line) = 2 lines
// per point-level. Lines: 92M (R4) -> 74M.

#define TABLE_SIZE (1u << 19)
#define HASH_MASK  (TABLE_SIZE - 1u)
#define P1 2654435761u
#define P2 805459861u
#define N_SMALL 9

// int(16 * 32**(i/15)) with host libm pow: level 9 = 127 (confirmed R1/R2).
__constant__ int d_res[16] = {16, 20, 25, 32, 40, 50, 64, 80,
                              101, 127, 161, 203, 256, 322, 406, 512};
// cumulative r^3 offsets for levels 0..8
__constant__ int d_start[N_SMALL] = {0, 4096, 12096, 27721, 60489,
                                     124489, 249489, 511633, 1023633};
#define DENSE_TOTAL 2053934

struct __align__(32) Quad { float4 h0, h1; };  // h0: y0 (z0,z1), h1: y1 (z0,z1)

__device__ float2 g_corner[DENSE_TOTAL];        // phase-1 temp, 16.4 MB
__device__ Quad   g_quad[DENSE_TOTAL];          // 65.7 MB, L2-resident

// q = trunc(((c/res + 1) * 0.5) * 2^18); division as div.full.f32 to match
// the XLA-GPU reference's fast-path lowering (bit-exact requirement, R3).
__device__ __forceinline__ unsigned qval(int c, float resf) {
    float d;
    asm("div.full.f32 %0, %1, %2;" : "=f"(d) : "f"((float)c), "f"(resf));
    float v = __fmul_rn(__fadd_rn(d, 1.0f), 131072.0f);
    return (unsigned)v;
}

// Phase 1: one hashed gather per unique dense corner (coalesced writes).
__global__ __launch_bounds__(256)
void pre_corners(const float2* __restrict__ tables) {
    int level = blockIdx.y;
    int r = d_res[level];
    int n = r * r * r;
    int i = blockIdx.x * blockDim.x + threadIdx.x;
    if (i >= n) return;
    int c = i % r;
    int t = i / r;
    int b = t % r;
    int a = t / r;
    float resf = (float)r;
    unsigned h = qval(a, resf) + qval(b, resf) * P1 + qval(c, resf) * P2;
    const float2* tab = tables + (size_t)level * TABLE_SIZE;
    g_corner[d_start[level] + i] = __ldg(&tab[h & HASH_MASK]);
}

// Phase 2: assemble 32B quad records (coalesced reads along z, coalesced writes).
__global__ __launch_bounds__(256)
void pre_quads() {
    int level = blockIdx.y;
    int r = d_res[level];
    int n = r * r * r;
    int i = blockIdx.x * blockDim.x + threadIdx.x;
    if (i >= n) return;
    int c = i % r;              // z
    int t = i / r;
    int b = t % r;              // y
    int a = t / r;              // x
    int b1 = (b + 1 == r) ? 0 : b + 1;
    int c1 = (c + 1 == r) ? 0 : c + 1;
    const float2* tc = g_corner + d_start[level];
    int r0 = (a * r + b) * r;
    int r1 = (a * r + b1) * r;
    float2 f00 = tc[r0 + c], f01 = tc[r0 + c1];
    float2 f10 = tc[r1 + c], f11 = tc[r1 + c1];
    Quad qd;
    qd.h0 = make_float4(f00.x, f00.y, f01.x, f01.y);
    qd.h1 = make_float4(f10.x, f10.y, f11.x, f11.y);
    g_quad[d_start[level] + i] = qd;
}

// Dense levels 0-8: 4 lanes per (point,level); lane q loads quarter q of the
// 64B need (x-side = q>>1, y-half = q&1). One LDG.128/lane, 2 lines/pl.
__global__ __launch_bounds__(256)
void encode_dense(const float* __restrict__ x,
                  float2* __restrict__ out, int n_pts)
{
    int t = blockIdx.x * blockDim.x + threadIdx.x;
    int q = t & 3;
    int qid = t >> 2;
    bool valid = qid < n_pts * N_SMALL;
    int cqid = valid ? qid : 0;
    int point = cqid / N_SMALL;
    int level = cqid - point * N_SMALL;

    float px = fminf(fmaxf(__ldg(x + 3 * point + 0), -1.0f), 1.0f);
    float py = fminf(fmaxf(__ldg(x + 3 * point + 1), -1.0f), 1.0f);
    float pz = fminf(fmaxf(__ldg(x + 3 * point + 2), -1.0f), 1.0f);

    int r = d_res[level];
    float resf = (float)r;
    float cx = __fmul_rn(px, resf);
    float cy = __fmul_rn(py, resf);
    float cz = __fmul_rn(pz, resf);
    float fx = floorf(cx), fy = floorf(cy), fz = floorf(cz);
    float lx = __fsub_rn(cx, fx);
    float ly = __fsub_rn(cy, fy);
    float lz = __fsub_rn(cz, fz);
    int ix = (int)fx, iy = (int)fy, iz = (int)fz;
    int x0 = ix; if (x0 < 0) x0 += r; else if (x0 >= r) x0 -= r;
    int x1 = ix + 1; if (x1 < 0) x1 += r; else if (x1 >= r) x1 -= r;
    int y0 = iy; if (y0 < 0) y0 += r; else if (y0 >= r) y0 -= r;
    int z0 = iz; if (z0 < 0) z0 += r; else if (z0 >= r) z0 -= r;

    int xs = (q >> 1) ? x1 : x0;
    int idx = d_start[level] + (xs * r + y0) * r + z0;
    const float4* recq = reinterpret_cast<const float4*>(&g_quad[idx]) + (q & 1);
    float4 v = __ldg(recq);

    float wq = ((q >> 1) ? lx : 1.0f - lx) * ((q & 1) ? ly : 1.0f - ly);
    float wz0 = 1.0f - lz;
    float pax = wq * (wz0 * v.x + lz * v.z);
    float pay = wq * (wz0 * v.y + lz * v.w);
    pax += __shfl_xor_sync(0xFFFFFFFFu, pax, 1);
    pay += __shfl_xor_sync(0xFFFFFFFFu, pay, 1);
    pax += __shfl_xor_sync(0xFFFFFFFFu, pax, 2);
    pay += __shfl_xor_sync(0xFFFFFFFFu, pay, 2);
    if (q == 0 && valid)
        out[(size_t)point * 16 + level] = make_float2(pax, pay);
}

// Hash levels 9-15: 8 scattered 8B gathers per (point,level). Proven at the
// wavefront floor (194us for 56M lines) in R5.
__global__ __launch_bounds__(256)
void encode_hash(const float* __restrict__ x,
                 const float2* __restrict__ tables,
                 float2* __restrict__ out, int n_pts)
{
    int t = blockIdx.x * blockDim.x + threadIdx.x;
    if (t >= n_pts * 7) return;
    int point = t / 7;
    int level = 9 + (t - point * 7);

    float px = fminf(fmaxf(__ldg(x + 3 * point + 0), -1.0f), 1.0f);
    float py = fminf(fmaxf(__ldg(x + 3 * point + 1), -1.0f), 1.0f);
    float pz = fminf(fmaxf(__ldg(x + 3 * point + 2), -1.0f), 1.0f);

    int res = d_res[level];
    float resf = (float)res;
    float cx = __fmul_rn(px, resf);
    float cy = __fmul_rn(py, resf);
    float cz = __fmul_rn(pz, resf);
    float fx = floorf(cx), fy = floorf(cy), fz = floorf(cz);
    float lx = __fsub_rn(cx, fx);
    float ly = __fsub_rn(cy, fy);
    float lz = __fsub_rn(cz, fz);
    int ix = (int)fx, iy = (int)fy, iz = (int)fz;

    int x0 = ix;     if (x0 < 0) x0 += res; else if (x0 >= res) x0 -= res;
    int x1 = ix + 1; if (x1 < 0) x1 += res; else if (x1 >= res) x1 -= res;
    int y0 = iy;     if (y0 < 0) y0 += res; else if (y0 >= res) y0 -= res;
    int y1 = iy + 1; if (y1 < 0) y1 += res; else if (y1 >= res) y1 -= res;
    int z0 = iz;     if (z0 < 0) z0 += res; else if (z0 >= res) z0 -= res;
    int z1 = iz + 1; if (z1 < 0) z1 += res; else if (z1 >= res) z1 -= res;

    unsigned hx[2], hy[2], hz[2];
    hx[0] = qval(x0, resf);
    hx[1] = qval(x1, resf);
    hy[0] = qval(y0, resf) * P1;
    hy[1] = qval(y1, resf) * P1;
    hz[0] = qval(z0, resf) * P2;
    hz[1] = qval(z1, resf) * P2;

    const float2* tab = tables + (size_t)level * TABLE_SIZE;
    float2 f[8];
#pragma unroll
    for (int c = 0; c < 8; c++) {
        unsigned idx = (hx[(c >> 2) & 1] + hy[(c >> 1) & 1] + hz[c & 1]) & HASH_MASK;
        f[c] = __ldg(&tab[idx]);
    }
    float wxa[2] = {1.0f - lx, lx};
    float wya[2] = {1.0f - ly, ly};
    float wza[2] = {1.0f - lz, lz};
    float ax = 0.0f, ay = 0.0f;
#pragma unroll
    for (int c = 0; c < 8; c++) {
        float w = wxa[(c >> 2) & 1] * wya[(c >> 1) & 1] * wza[c & 1];
        ax += w * f[c].x;
        ay += w * f[c].y;
    }
    out[(size_t)point * 16 + level] = make_float2(ax, ay);
}

extern "C" void kernel_launch(void* const* d_in, const int* in_sizes, int n_in,
                              void* d_out, int out_size) {
    const float* x = (const float*)d_in[0];
    const float2* tables = (const float2*)d_in[1];
    float2* out = (float2*)d_out;
    int n_pts = in_sizes[0] / 3;

    dim3 pre_grid((1030301 + 255) / 256, N_SMALL);   // max r^3 = 101^3
    pre_corners<<<pre_grid, 256>>>(tables);
    pre_quads<<<pre_grid, 256>>>();

    long long nd = (long long)n_pts * N_SMALL * 4;
    encode_dense<<<(int)((nd + 255) / 256), 256>>>(x, out, n_pts);

    long long nh = (long long)n_pts * 7;
    encode_hash<<<(int)((nh + 255) / 256), 256>>>(x, tables, out, n_pts);
}